// round 11
// baseline (speedup 1.0000x reference)
#include <cuda_runtime.h>
#include <cstdint>

namespace {

constexpr int BATCH     = 20000;
constexpr int MTOT      = 49;
constexpr int KDIM      = 128;
constexpr int NDIM      = 128;
constexpr int TILE_ROWS = 128;
constexpr int NTILES    = 4;                      // row-tiles per CTA (best: R8)
constexpr int NTHREADS  = 256;

constexpr int PLANE      = 16384;                 // W plane: 128 n-rows x 128B (64 fp16 k)
constexpr int SMEM_TOTAL = 2 * PLANE;             // W only: 32 KB

constexpr size_t ROW_STRIDE = (size_t)MTOT * KDIM;   // floats between batch rows

// W in smem: SW128-style, row=128B, seg' = seg ^ (row&7); ldmatrix.x4.b16 consumer
// (mapping validated R5-R8). A: direct LDG.64 -> cvt.rn.f16x2 fragments, no smem.

__device__ __forceinline__ uint32_t smem_u32(const void* p) {
    uint32_t a;
    asm("{ .reg .u64 t; cvta.to.shared.u64 t, %1; cvt.u32.u64 %0, t; }"
        : "=r"(a) : "l"(p));
    return a;
}

__device__ __forceinline__ uint32_t f16x2(float lo, float hi) {
    uint32_t r;                    // low half = lo (lower k index)
    asm("cvt.rn.f16x2.f32 %0, %2, %1;" : "=r"(r) : "f"(lo), "f"(hi));
    return r;
}

__device__ __forceinline__ void sts128(uint32_t addr, uint32_t a, uint32_t b,
                                       uint32_t c, uint32_t d) {
    asm volatile("st.shared.v4.b32 [%0], {%1, %2, %3, %4};"
                 :: "r"(addr), "r"(a), "r"(b), "r"(c), "r"(d) : "memory");
}

__device__ __forceinline__ void ldsm4(uint32_t& r0, uint32_t& r1,
                                      uint32_t& r2, uint32_t& r3, uint32_t addr) {
    asm volatile("ldmatrix.sync.aligned.m8n8.x4.shared.b16 {%0,%1,%2,%3}, [%4];"
                 : "=r"(r0), "=r"(r1), "=r"(r2), "=r"(r3) : "r"(addr));
}

__device__ __forceinline__ void mma_f16(float* c, uint32_t a0, uint32_t a1,
                                        uint32_t a2, uint32_t a3,
                                        uint32_t b0, uint32_t b1) {
    asm volatile(
        "mma.sync.aligned.m16n8k16.row.col.f32.f16.f16.f32 "
        "{%0,%1,%2,%3}, {%4,%5,%6,%7}, {%8,%9}, {%0,%1,%2,%3};"
        : "+f"(c[0]), "+f"(c[1]), "+f"(c[2]), "+f"(c[3])
        : "r"(a0), "r"(a1), "r"(a2), "r"(a3), "r"(b0), "r"(b1));
}

__global__ void __launch_bounds__(NTHREADS, 2)
so3_linear_kernel(const float* __restrict__ in,
                  const float* __restrict__ w,
                  const float* __restrict__ bias,
                  float* __restrict__ out)
{
    extern __shared__ char smem[];
    const uint32_t sb = smem_u32(smem);

    const int tid  = threadIdx.x;
    const int lane = tid & 31;
    const int wid  = tid >> 5;
    const int g    = lane >> 2;
    const int t    = lane & 3;

    const int m = blockIdx.y;
    int l = 0;
    while ((l + 1) * (l + 1) <= m) l++;
    const float* wl = w + (size_t)l * NDIM * KDIM;

    // ---- W prologue: stage 128x128 fp16, SW128 layout (identical to R8) ----
    {
        const int prow = tid >> 3;
        const int seg  = tid & 7;
        const uint32_t stsOff0 = (uint32_t)(prow * 128 + ((seg ^ (prow & 7)) << 4));
        const float* wRow = wl + (size_t)prow * KDIM + seg * 8;
        #pragma unroll
        for (int p = 0; p < 2; p++) {
            const uint32_t wb = sb + (uint32_t)(p * PLANE) + stsOff0;
            #pragma unroll
            for (int i = 0; i < 4; i++) {
                const float* q = wRow + i * (32 * KDIM) + p * 64;
                float4 q0 = *reinterpret_cast<const float4*>(q);
                float4 q1 = *reinterpret_cast<const float4*>(q + 4);
                sts128(wb + i * 4096,
                       f16x2(q0.x, q0.y), f16x2(q0.z, q0.w),
                       f16x2(q1.x, q1.y), f16x2(q1.z, q1.w));
            }
        }
    }

    // ---- consumer mapping ----
    const int warp_row = (wid & 3) * 32;
    const int warp_col = (wid >> 2) * 64;
    const int x7 = lane & 7;
    const int bRowOff = ((lane >> 4) & 1) * 8 + x7;
    const int bSh     = (lane >> 3) & 1;
    const uint32_t bBaseOff = (uint32_t)((warp_col + bRowOff) * 128);
    uint32_t bSegT[4];
    #pragma unroll
    for (int ks = 0; ks < 4; ks++)
        bSegT[ks] = (uint32_t)(((2 * ks + bSh) ^ x7) << 4);

    const int rowBase0 = blockIdx.x * (NTILES * TILE_ROWS);
    const int nt = min(NTILES, (BATCH - rowBase0 + TILE_ROWS - 1) / TILE_ROWS);

    // A direct-load: per thread 4 rows (g, g+8, g+16, g+24 within warp_row block)
    int rowIdx[4];
    #pragma unroll
    for (int i = 0; i < 4; i++)
        rowIdx[i] = rowBase0 + warp_row + g + i * 8;
    const float* aT = in + (size_t)m * KDIM + 2 * t;   // + r*ROW_STRIDE + kb

    float2 raw[8];
    auto prefetchA = [&](int tl, int h, int ks) {
        const int kb = h * 64 + ks * 16;
        #pragma unroll
        for (int i = 0; i < 4; i++) {
            int r = rowIdx[i] + tl * TILE_ROWS;
            if (r >= BATCH) r = BATCH - 1;           // clamped rows never stored
            const float* p = aT + (size_t)r * ROW_STRIDE + kb;
            raw[2 * i]     = *reinterpret_cast<const float2*>(p);      // k 2t,2t+1
            raw[2 * i + 1] = *reinterpret_cast<const float2*>(p + 8);  // k 2t+8,+9
        }
    };

    prefetchA(0, 0, 0);
    __syncthreads();                                  // W visible; only barrier

    float acc[2][8][4] = {};
    const bool addb = (m == 0);

    for (int tl = 0; tl < nt; tl++) {
        #pragma unroll
        for (int h = 0; h < 2; h++) {
            #pragma unroll
            for (int ks = 0; ks < 4; ks++) {
                // assemble A fragments for this k16 step (numerics == R8)
                uint32_t a0[4], a1[4];
                a0[0] = f16x2(raw[0].x, raw[0].y);   // row g,    k 2t
                a0[1] = f16x2(raw[2].x, raw[2].y);   // row g+8
                a0[2] = f16x2(raw[1].x, raw[1].y);   // row g,    k 2t+8
                a0[3] = f16x2(raw[3].x, raw[3].y);   // row g+8
                a1[0] = f16x2(raw[4].x, raw[4].y);   // row g+16
                a1[1] = f16x2(raw[6].x, raw[6].y);   // row g+24
                a1[2] = f16x2(raw[5].x, raw[5].y);
                a1[3] = f16x2(raw[7].x, raw[7].y);

                // prefetch next k16 step (distance 1; covered by 16 MMAs)
                int nks = ks + 1, nh = h, ntl = tl;
                if (nks == 4) { nks = 0; if (++nh == 2) { nh = 0; ntl++; } }
                if (ntl < nt) prefetchA(ntl, nh, nks);

                const uint32_t Wb = sb + (uint32_t)(h * PLANE) + bBaseOff;
                #pragma unroll
                for (int np = 0; np < 4; np++) {
                    uint32_t b0, b1, b2, b3;
                    ldsm4(b0, b1, b2, b3, Wb + (uint32_t)(np * 2048) + bSegT[ks]);
                    mma_f16(acc[0][2 * np],     a0[0], a0[1], a0[2], a0[3], b0, b1);
                    mma_f16(acc[0][2 * np + 1], a0[0], a0[1], a0[2], a0[3], b2, b3);
                    mma_f16(acc[1][2 * np],     a1[0], a1[1], a1[2], a1[3], b0, b1);
                    mma_f16(acc[1][2 * np + 1], a1[0], a1[1], a1[2], a1[3], b2, b3);
                }
            }
        }

        // ---- epilogue tile tl (no barriers anywhere in steady state) ----
        const int rb = rowBase0 + tl * TILE_ROWS;
        #pragma unroll
        for (int mi = 0; mi < 2; mi++) {
            #pragma unroll
            for (int ni = 0; ni < 8; ni++) {
                const int cc = warp_col + ni * 8 + 2 * t;
                const int r0 = rb + warp_row + mi * 16 + g;
                float2 v0 = make_float2(acc[mi][ni][0], acc[mi][ni][1]);
                float2 v1 = make_float2(acc[mi][ni][2], acc[mi][ni][3]);
                if (addb) {
                    const float b0v = bias[cc], b1v = bias[cc + 1];
                    v0.x += b0v; v0.y += b1v;
                    v1.x += b0v; v1.y += b1v;
                }
                if (r0 < BATCH)
                    *reinterpret_cast<float2*>(out + (((size_t)r0 * MTOT + m) * NDIM + cc)) = v0;
                if (r0 + 8 < BATCH)
                    *reinterpret_cast<float2*>(out + (((size_t)(r0 + 8) * MTOT + m) * NDIM + cc)) = v1;
                acc[mi][ni][0] = 0.f; acc[mi][ni][1] = 0.f;
                acc[mi][ni][2] = 0.f; acc[mi][ni][3] = 0.f;
            }
        }
    }
}

}  // namespace

extern "C" void kernel_launch(void* const* d_in, const int* in_sizes, int n_in,
                              void* d_out, int out_size) {
    (void)in_sizes; (void)n_in; (void)out_size;
    const float* in   = (const float*)d_in[0];
    const float* w    = (const float*)d_in[1];
    const float* bias = (const float*)d_in[2];
    float* out        = (float*)d_out;

    cudaFuncSetAttribute(so3_linear_kernel,
                         cudaFuncAttributeMaxDynamicSharedMemorySize, SMEM_TOTAL);

    dim3 grid((BATCH + NTILES * TILE_ROWS - 1) / (NTILES * TILE_ROWS), MTOT);
    so3_linear_kernel<<<grid, NTHREADS, SMEM_TOTAL>>>(in, w, bias, out);
}

// round 12
// speedup vs baseline: 1.1149x; 1.1149x over previous
#include <cuda_runtime.h>
#include <cstdint>

namespace {

constexpr int BATCH     = 20000;
constexpr int MTOT      = 49;
constexpr int KDIM      = 128;
constexpr int NDIM      = 128;
constexpr int TILE_ROWS = 128;
constexpr int NTILES    = 4;                      // row-tiles per CTA
constexpr int NTHREADS  = 256;

constexpr int PLANE_A    = 16384;                 // A plane: 128 rows x 128B (64 fp16 k)
constexpr int PLANE_W    = 8192;                  // W plane: 64 n-rows x 128B
constexpr int W_OFF      = 3 * PLANE_A;           // A triple-buffer ring first
constexpr int SMEM_TOTAL = W_OFF + 2 * PLANE_W;   // 48KB A + 16KB W = 65536 B

constexpr size_t ROW_STRIDE = (size_t)MTOT * KDIM;   // floats between batch rows

// SW128-style layout: smem row = 128B (64 fp16 k), 8 x 16B segs, seg' = seg^(row&7).
// Consumer: ldmatrix.m8n8.x4.b16 -> m16n8k16 fp16 mma (mapping validated R5-R8).
// N-split: each CTA computes 64 of the 128 output columns (nhalf = blockIdx.x & 1).

__device__ __forceinline__ uint32_t smem_u32(const void* p) {
    uint32_t a;
    asm("{ .reg .u64 t; cvta.to.shared.u64 t, %1; cvt.u32.u64 %0, t; }"
        : "=r"(a) : "l"(p));
    return a;
}

__device__ __forceinline__ uint32_t f16x2(float lo, float hi) {
    uint32_t r;                    // low half = lo (lower k index)
    asm("cvt.rn.f16x2.f32 %0, %2, %1;" : "=r"(r) : "f"(lo), "f"(hi));
    return r;
}

__device__ __forceinline__ void sts128(uint32_t addr, uint32_t a, uint32_t b,
                                       uint32_t c, uint32_t d) {
    asm volatile("st.shared.v4.b32 [%0], {%1, %2, %3, %4};"
                 :: "r"(addr), "r"(a), "r"(b), "r"(c), "r"(d) : "memory");
}

__device__ __forceinline__ void ldsm4(uint32_t& r0, uint32_t& r1,
                                      uint32_t& r2, uint32_t& r3, uint32_t addr) {
    asm volatile("ldmatrix.sync.aligned.m8n8.x4.shared.b16 {%0,%1,%2,%3}, [%4];"
                 : "=r"(r0), "=r"(r1), "=r"(r2), "=r"(r3) : "r"(addr));
}

__device__ __forceinline__ void mma_f16(float* c, uint32_t a0, uint32_t a1,
                                        uint32_t a2, uint32_t a3,
                                        uint32_t b0, uint32_t b1) {
    asm volatile(
        "mma.sync.aligned.m16n8k16.row.col.f32.f16.f16.f32 "
        "{%0,%1,%2,%3}, {%4,%5,%6,%7}, {%8,%9}, {%0,%1,%2,%3};"
        : "+f"(c[0]), "+f"(c[1]), "+f"(c[2]), "+f"(c[3])
        : "r"(a0), "r"(a1), "r"(a2), "r"(a3), "r"(b0), "r"(b1));
}

__global__ void __launch_bounds__(NTHREADS, 3)
so3_linear_kernel(const float* __restrict__ in,
                  const float* __restrict__ w,
                  const float* __restrict__ bias,
                  float* __restrict__ out)
{
    extern __shared__ char smem[];
    const uint32_t sb = smem_u32(smem);

    const int tid  = threadIdx.x;
    const int lane = tid & 31;
    const int wid  = tid >> 5;
    const int g    = lane >> 2;
    const int t    = lane & 3;

    const int m = blockIdx.y;
    int l = 0;
    while ((l + 1) * (l + 1) <= m) l++;
    const float* wl = w + (size_t)l * NDIM * KDIM;

    const int rowGroup = blockIdx.x >> 1;
    const int nhalf    = blockIdx.x & 1;

    // ---- producer mapping: 8 threads/row, 32B fp32 -> 16B fp16 seg ----
    const int prow = tid >> 3;               // 0..31
    const int seg  = tid & 7;
    const uint32_t stsOff0 = (uint32_t)(prow * 128 + ((seg ^ (prow & 7)) << 4));

    const int rowBase0 = rowGroup * (NTILES * TILE_ROWS);
    const int nt = min(NTILES, (BATCH - rowBase0 + TILE_ROWS - 1) / TILE_ROWS);
    const int nchunks = nt * 2;              // k64 planes per row-group

    const float* aCol = in + (size_t)m * KDIM + seg * 8;

    float st[2][8];                           // staged fp32: half a plane (2 row-blocks)

    auto ldgHalf = [&](int gj, int half) {
        if (gj >= nchunks) return;
        const int tl = gj >> 1, h = gj & 1;
        #pragma unroll
        for (int i2 = 0; i2 < 2; i2++) {
            const int i = half * 2 + i2;
            int r = rowBase0 + tl * TILE_ROWS + prow + 32 * i;
            if (r >= BATCH) r = BATCH - 1;   // clamped rows never stored
            const float* p = aCol + (size_t)r * ROW_STRIDE + h * 64;
            float4 q0 = *reinterpret_cast<const float4*>(p);
            float4 q1 = *reinterpret_cast<const float4*>(p + 4);
            st[i2][0] = q0.x; st[i2][1] = q0.y; st[i2][2] = q0.z; st[i2][3] = q0.w;
            st[i2][4] = q1.x; st[i2][5] = q1.y; st[i2][6] = q1.z; st[i2][7] = q1.w;
        }
    };
    auto stsHalf = [&](int gj, int half) {
        if (gj >= nchunks) return;
        const uint32_t ad = sb + (uint32_t)((gj % 3) * PLANE_A + half * 8192) + stsOff0;
        #pragma unroll
        for (int i2 = 0; i2 < 2; i2++)
            sts128(ad + i2 * 4096,
                   f16x2(st[i2][0], st[i2][1]), f16x2(st[i2][2], st[i2][3]),
                   f16x2(st[i2][4], st[i2][5]), f16x2(st[i2][6], st[i2][7]));
    };

    // ---- prologue: plane0 fully staged; plane1 half0 in regs; W staged ----
    ldgHalf(0, 0); stsHalf(0, 0);
    ldgHalf(0, 1); stsHalf(0, 1);
    ldgHalf(1, 0);

    {   // W: this CTA's 64 n-rows x 128 k, 2 planes of k64
        const float* wRow = wl + (size_t)(nhalf * 64 + prow) * KDIM + seg * 8;
        #pragma unroll
        for (int p = 0; p < 2; p++) {
            const uint32_t wb = sb + (uint32_t)(W_OFF + p * PLANE_W) + stsOff0;
            #pragma unroll
            for (int i = 0; i < 2; i++) {           // n-rows prow, prow+32
                const float* q = wRow + i * (32 * KDIM) + p * 64;
                float4 q0 = *reinterpret_cast<const float4*>(q);
                float4 q1 = *reinterpret_cast<const float4*>(q + 4);
                sts128(wb + i * 4096,
                       f16x2(q0.x, q0.y), f16x2(q0.z, q0.w),
                       f16x2(q1.x, q1.y), f16x2(q1.z, q1.w));
            }
        }
    }
    __syncthreads();

    // ---- consumer mapping (R5-R8 formulas; warp grid 4 rows x 2 cols of 32) ----
    const int warp_row  = (wid & 3) * 32;
    const int warp_colL = (wid >> 2) * 32;            // local col within 64
    const int x7 = lane & 7;
    const int aRowOff = ((lane >> 3) & 1) * 8 + x7;
    const int aSh     = lane >> 4;
    const int bRowOff = ((lane >> 4) & 1) * 8 + x7;
    const int bSh     = (lane >> 3) & 1;
    const uint32_t aBaseOff = (uint32_t)((warp_row + aRowOff) * 128);
    const uint32_t bBaseOff = (uint32_t)((warp_colL + bRowOff) * 128);
    uint32_t aSegT[4], bSegT[4];
    #pragma unroll
    for (int ks = 0; ks < 4; ks++) {
        aSegT[ks] = (uint32_t)(((2 * ks + aSh) ^ x7) << 4);
        bSegT[ks] = (uint32_t)(((2 * ks + bSh) ^ x7) << 4);
    }

    float acc[2][4][4] = {};
    const bool addb = (m == 0);

    for (int gj = 0; gj < nchunks; gj++) {
        const int h = gj & 1;
        const uint32_t Ab = sb + (uint32_t)((gj % 3) * PLANE_A) + aBaseOff;
        const uint32_t Wb = sb + (uint32_t)(W_OFF + h * PLANE_W) + bBaseOff;

        stsHalf(gj + 1, 0);                   // staged during previous iteration
        ldgHalf(gj + 1, 1);

        #pragma unroll
        for (int ks = 0; ks < 2; ks++) {
            uint32_t af[4], ag[4], b0, b1, b2, b3;
            ldsm4(af[0], af[1], af[2], af[3], Ab + aSegT[ks]);
            ldsm4(ag[0], ag[1], ag[2], ag[3], Ab + 2048 + aSegT[ks]);
            #pragma unroll
            for (int np = 0; np < 2; np++) {
                ldsm4(b0, b1, b2, b3, Wb + (uint32_t)(np * 2048) + bSegT[ks]);
                mma_f16(acc[0][2 * np],     af[0], af[1], af[2], af[3], b0, b1);
                mma_f16(acc[0][2 * np + 1], af[0], af[1], af[2], af[3], b2, b3);
                mma_f16(acc[1][2 * np],     ag[0], ag[1], ag[2], ag[3], b0, b1);
                mma_f16(acc[1][2 * np + 1], ag[0], ag[1], ag[2], ag[3], b2, b3);
            }
        }

        stsHalf(gj + 1, 1);
        ldgHalf(gj + 2, 0);

        #pragma unroll
        for (int ks = 2; ks < 4; ks++) {
            uint32_t af[4], ag[4], b0, b1, b2, b3;
            ldsm4(af[0], af[1], af[2], af[3], Ab + aSegT[ks]);
            ldsm4(ag[0], ag[1], ag[2], ag[3], Ab + 2048 + aSegT[ks]);
            #pragma unroll
            for (int np = 0; np < 2; np++) {
                ldsm4(b0, b1, b2, b3, Wb + (uint32_t)(np * 2048) + bSegT[ks]);
                mma_f16(acc[0][2 * np],     af[0], af[1], af[2], af[3], b0, b1);
                mma_f16(acc[0][2 * np + 1], af[0], af[1], af[2], af[3], b2, b3);
                mma_f16(acc[1][2 * np],     ag[0], ag[1], ag[2], ag[3], b0, b1);
                mma_f16(acc[1][2 * np + 1], ag[0], ag[1], ag[2], ag[3], b2, b3);
            }
        }

        if (h == 1) {
            // ---- epilogue for tile gj>>1 ----
            const int rb = rowBase0 + (gj >> 1) * TILE_ROWS;
            #pragma unroll
            for (int mi = 0; mi < 2; mi++) {
                #pragma unroll
                for (int ni = 0; ni < 4; ni++) {
                    const int cc = nhalf * 64 + warp_colL + ni * 8 + 2 * t;
                    const int r0 = rb + warp_row + mi * 16 + g;
                    float2 v0 = make_float2(acc[mi][ni][0], acc[mi][ni][1]);
                    float2 v1 = make_float2(acc[mi][ni][2], acc[mi][ni][3]);
                    if (addb) {
                        const float b0v = bias[cc], b1v = bias[cc + 1];
                        v0.x += b0v; v0.y += b1v;
                        v1.x += b0v; v1.y += b1v;
                    }
                    if (r0 < BATCH)
                        *reinterpret_cast<float2*>(out + (((size_t)r0 * MTOT + m) * NDIM + cc)) = v0;
                    if (r0 + 8 < BATCH)
                        *reinterpret_cast<float2*>(out + (((size_t)(r0 + 8) * MTOT + m) * NDIM + cc)) = v1;
                    acc[mi][ni][0] = 0.f; acc[mi][ni][1] = 0.f;
                    acc[mi][ni][2] = 0.f; acc[mi][ni][3] = 0.f;
                }
            }
        }
        __syncthreads();
    }
}

}  // namespace

extern "C" void kernel_launch(void* const* d_in, const int* in_sizes, int n_in,
                              void* d_out, int out_size) {
    (void)in_sizes; (void)n_in; (void)out_size;
    const float* in   = (const float*)d_in[0];
    const float* w    = (const float*)d_in[1];
    const float* bias = (const float*)d_in[2];
    float* out        = (float*)d_out;

    cudaFuncSetAttribute(so3_linear_kernel,
                         cudaFuncAttributeMaxDynamicSharedMemorySize, SMEM_TOTAL);

    dim3 grid(2 * ((BATCH + NTILES * TILE_ROWS - 1) / (NTILES * TILE_ROWS)), MTOT);
    so3_linear_kernel<<<grid, NTHREADS, SMEM_TOTAL>>>(in, w, bias, out);
}